// round 8
// baseline (speedup 1.0000x reference)
#include <cuda_runtime.h>
#include <cuda_fp16.h>
#include <math.h>
#include <stdint.h>

#define SQ     2048
#define BATCH  2
#define HID    4096
#define QKV_O  6144
#define NHEADS 32
#define KVH    8
#define HD     128
#define MROWS  (BATCH*SQ)   // 4096

// ---------------- scratch (allocation-free rule) ----------------
__device__ float  g_qkv  [(size_t)MROWS * QKV_O];
__device__ __half g_qkv16[(size_t)MROWS * QKV_O];
__device__ __half g_hs16  [(size_t)MROWS * HID];
__device__ __half g_wqkv16[(size_t)QKV_O * HID];
__device__ __half g_wo16  [(size_t)HID   * HID];
__device__ __half g_attn16[(size_t)MROWS * HID];

// ---------------- helpers ----------------
__device__ __forceinline__ uint32_t smem_u32(const void* p) {
    uint32_t a;
    asm("{ .reg .u64 t; cvta.to.shared.u64 t, %1; cvt.u32.u64 %0, t; }" : "=r"(a) : "l"(p));
    return a;
}
#define CP_ASYNC16(dst, src) \
    asm volatile("cp.async.cg.shared.global [%0], [%1], 16;" :: "r"(dst), "l"(src))
#define CP_COMMIT()  asm volatile("cp.async.commit_group;" ::: "memory")
#define CP_WAIT1()   asm volatile("cp.async.wait_group 1;" ::: "memory")
#define CP_WAIT0()   asm volatile("cp.async.wait_group 0;" ::: "memory")

__device__ __forceinline__ void ldm_x4(uint32_t& r0, uint32_t& r1, uint32_t& r2, uint32_t& r3,
                                       uint32_t addr) {
    asm volatile("ldmatrix.sync.aligned.m8n8.x4.shared.b16 {%0,%1,%2,%3}, [%4];"
                 : "=r"(r0), "=r"(r1), "=r"(r2), "=r"(r3) : "r"(addr));
}
__device__ __forceinline__ void ldm_x4_t(uint32_t& r0, uint32_t& r1, uint32_t& r2, uint32_t& r3,
                                         uint32_t addr) {
    asm volatile("ldmatrix.sync.aligned.m8n8.x4.trans.shared.b16 {%0,%1,%2,%3}, [%4];"
                 : "=r"(r0), "=r"(r1), "=r"(r2), "=r"(r3) : "r"(addr));
}
__device__ __forceinline__ void mma16816(float* c, const uint32_t* a, uint32_t b0, uint32_t b1) {
    asm volatile("mma.sync.aligned.m16n8k16.row.col.f32.f16.f16.f32 "
                 "{%0,%1,%2,%3}, {%4,%5,%6,%7}, {%8,%9}, {%0,%1,%2,%3};"
                 : "+f"(c[0]), "+f"(c[1]), "+f"(c[2]), "+f"(c[3])
                 : "r"(a[0]), "r"(a[1]), "r"(a[2]), "r"(a[3]), "r"(b0), "r"(b1));
}
__device__ __forceinline__ uint32_t f22h(float a, float b) {
    union { __half2 h; uint32_t u; } x;
    x.h = __floats2half2_rn(a, b);
    return x.u;
}

// ---------------------------------------------------------------------------
// fp16 mma.sync GEMM:  C[M,N] (fp32) = A16[M,K] * B16[N,K]^T
// CTA 128x128, BK=64, 3-stage cp.async pipeline, ONE __syncthreads per
// mainloop iteration (WAR-safe: load at iter kt writes stage (kt-1)%3 whose
// compute ended before this iter's barrier). 108KB dynamic smem, 2 CTA/SM.
// ---------------------------------------------------------------------------
#define GLD2 72
#define GSTG (128 * GLD2)                  // halfs per (A or B) stage half-buffer
#define GEMM_SMEM (6 * GSTG * 2)           // 3 stages * (A+B) * 2B = 110592 B

__global__ void __launch_bounds__(256, 2) hgemm_mma(
    const __half* __restrict__ A, const __half* __restrict__ B,
    float* __restrict__ C, int N, int K)
{
    extern __shared__ __align__(16) __half smg[];
    uint32_t sAu[3], sBu[3];
    #pragma unroll
    for (int s = 0; s < 3; ++s) {
        sAu[s] = smem_u32(smg + (2 * s) * GSTG);
        sBu[s] = smem_u32(smg + (2 * s + 1) * GSTG);
    }

    const int tid  = threadIdx.x;
    const int lane = tid & 31;
    const int wid  = tid >> 5;
    const int wr   = wid >> 2;
    const int wc   = wid & 3;
    const int rowBase = blockIdx.y * 128;
    const int colBase = blockIdx.x * 128;

    const __half* Ab = A + (size_t)rowBase * K;
    const __half* Bb = B + (size_t)colBase * K;

    auto load_tile = [&](int buf, int kt) {
        const __half* a = Ab + kt * 64;
        const __half* b = Bb + kt * 64;
        #pragma unroll
        for (int it = 0; it < 4; ++it) {
            int idx = tid + it * 256;
            int r = idx >> 3, c = idx & 7;
            CP_ASYNC16(sAu[buf] + (r * GLD2 + c * 8) * 2, a + (size_t)r * K + c * 8);
        }
        #pragma unroll
        for (int it = 0; it < 4; ++it) {
            int idx = tid + it * 256;
            int r = idx >> 3, c = idx & 7;
            CP_ASYNC16(sBu[buf] + (r * GLD2 + c * 8) * 2, b + (size_t)r * K + c * 8);
        }
    };

    float acc[4][4][4];
    #pragma unroll
    for (int i = 0; i < 4; ++i)
        #pragma unroll
        for (int j = 0; j < 4; ++j)
            #pragma unroll
            for (int r = 0; r < 4; ++r) acc[i][j][r] = 0.f;

    const int g  = lane >> 3;
    const int lr = lane & 7;
    const int a_row = wr * 64 + lr + (g & 1) * 8;
    const int a_kh  = (g >> 1) * 8;
    const int b_row = wc * 32 + lr + (g >> 1) * 8;
    const int b_kh  = (g & 1) * 8;

    // prologue: 2 tiles in flight
    load_tile(0, 0); CP_COMMIT();
    load_tile(1, 1); CP_COMMIT();

    const int NT = K / 64;
    int buf = 0;
    for (int kt = 0; kt < NT; ++kt) {
        // tile kt arrived when at most 1 newer group is pending
        if (kt < NT - 1) { CP_WAIT1(); } else { CP_WAIT0(); }
        __syncthreads();

        // prefetch tile kt+2 into stage (kt+2)%3 == (kt-1)%3 (compute of kt-1
        // finished before the barrier above — WAR safe)
        if (kt + 2 < NT) {
            int nbuf = buf + 2; if (nbuf >= 3) nbuf -= 3;
            load_tile(nbuf, kt + 2);
            CP_COMMIT();
        }

        #pragma unroll
        for (int s = 0; s < 4; ++s) {
            uint32_t af[4][4];
            #pragma unroll
            for (int i = 0; i < 4; ++i)
                ldm_x4(af[i][0], af[i][1], af[i][2], af[i][3],
                       sAu[buf] + ((a_row + i * 16) * GLD2 + s * 16 + a_kh) * 2);
            uint32_t bf[8];
            #pragma unroll
            for (int j2 = 0; j2 < 2; ++j2)
                ldm_x4(bf[j2 * 4 + 0], bf[j2 * 4 + 1], bf[j2 * 4 + 2], bf[j2 * 4 + 3],
                       sBu[buf] + ((b_row + j2 * 16) * GLD2 + s * 16 + b_kh) * 2);
            #pragma unroll
            for (int i = 0; i < 4; ++i)
                #pragma unroll
                for (int j = 0; j < 4; ++j)
                    mma16816(acc[i][j], af[i], bf[j * 2], bf[j * 2 + 1]);
        }

        if (++buf == 3) buf = 0;
    }

    const int em = lane >> 2;
    const int en = (lane & 3) * 2;
    #pragma unroll
    for (int i = 0; i < 4; ++i) {
        int m0 = rowBase + wr * 64 + i * 16 + em;
        #pragma unroll
        for (int j = 0; j < 4; ++j) {
            int n0 = colBase + wc * 32 + j * 8 + en;
            *(float2*)(C + (size_t)m0 * N + n0)       = make_float2(acc[i][j][0], acc[i][j][1]);
            *(float2*)(C + (size_t)(m0 + 8) * N + n0) = make_float2(acc[i][j][2], acc[i][j][3]);
        }
    }
}

// ---------------------------------------------------------------------------
// fp32 -> fp16 conversion (inputs/weights)
// ---------------------------------------------------------------------------
__global__ void cvt16(const float* __restrict__ in, __half* __restrict__ out, int n)
{
    int i = (blockIdx.x * blockDim.x + threadIdx.x) * 4;
    if (i >= n) return;
    float4 v = *(const float4*)(in + i);
    union { uint2 u; __half2 h[2]; } pk;
    pk.h[0] = __floats2half2_rn(v.x, v.y);
    pk.h[1] = __floats2half2_rn(v.z, v.w);
    *(uint2*)(out + i) = pk.u;
}

// ---------------------------------------------------------------------------
// Fused RoPE + fp32->fp16 (unchanged — validated round 7)
// ---------------------------------------------------------------------------
__global__ void rope_cvt(const float* __restrict__ qkv, __half* __restrict__ qkv16,
                         const int* __restrict__ positions)
{
    int t = blockIdx.x * blockDim.x + threadIdx.x;
    int r = t / 3072;
    int u = t - r * 3072;
    if (r >= MROWS) return;

    const float* src = qkv   + (size_t)r * QKV_O;
    __half*      dst = qkv16 + (size_t)r * QKV_O;

    if (u < 2560) {
        int h = u >> 6, p = u & 63;
        int col = (h < NHEADS) ? h * HD : HID + (h - NHEADS) * HD;
        float pos = (float)positions[r];
        float inv = expf((float)p * (-13.815510557964274f / 64.f));
        float ang = pos * inv;
        float sn, cs;
        sincosf(ang, &sn, &cs);
        float x1 = src[col + p];
        float x2 = src[col + p + 64];
        dst[col + p]      = __float2half_rn(x1 * cs - x2 * sn);
        dst[col + p + 64] = __float2half_rn(x2 * cs + x1 * sn);
    } else {
        int c = 5120 + ((u - 2560) << 1);
        float2 v = *(const float2*)(src + c);
        *(__half2*)(dst + c) = __floats2half2_rn(v.x, v.y);
    }
}

// ---------------------------------------------------------------------------
// fp16 tensor-core flash attention (unchanged — validated rounds 5/7)
// ---------------------------------------------------------------------------
#define KV_LD 136
#define KV_TILE (64 * KV_LD)
#define ATTN_SMEM (4 * KV_TILE * 2)

__global__ void __launch_bounds__(256, 1) attn16_kernel(
    const __half* __restrict__ qkv16, __half* __restrict__ attnh)
{
    extern __shared__ __align__(16) __half smh[];
    const int tid  = threadIdx.x;
    const int lane = tid & 31;
    const int wm   = tid >> 5;
    const int lr   = lane & 7;
    const int lg   = lane >> 3;
    const int qt = blockIdx.x, h = blockIdx.y, b = blockIdx.z;
    const int g  = h >> 2;
    const float scale = 0.08838834764831845f;

    const uint32_t ks[2] = { smem_u32(smh),           smem_u32(smh + 2 * KV_TILE) };
    const uint32_t vs[2] = { smem_u32(smh + KV_TILE), smem_u32(smh + 3 * KV_TILE) };

    const int t0 = b * SQ + qt * 128;
    const int r0 = lane >> 2;
    const int c0 = (lane & 3) * 2;

    uint32_t qf[8][4];
    {
        const __half* qp = qkv16 + (size_t)(t0 + wm * 16) * QKV_O + h * HD;
        #pragma unroll
        for (int kc = 0; kc < 8; ++kc) {
            qf[kc][0] = *(const uint32_t*)(qp + (size_t)r0 * QKV_O + kc * 16 + c0);
            qf[kc][1] = *(const uint32_t*)(qp + (size_t)(r0 + 8) * QKV_O + kc * 16 + c0);
            qf[kc][2] = *(const uint32_t*)(qp + (size_t)r0 * QKV_O + kc * 16 + 8 + c0);
            qf[kc][3] = *(const uint32_t*)(qp + (size_t)(r0 + 8) * QKV_O + kc * 16 + 8 + c0);
        }
    }

    float o[16][4];
    #pragma unroll
    for (int i = 0; i < 16; ++i)
        #pragma unroll
        for (int r = 0; r < 4; ++r) o[i][r] = 0.f;
    float m_i[2] = { -1e30f, -1e30f };
    float l_i[2] = { 0.f, 0.f };

    const __half* kbase = qkv16 + (size_t)(b * SQ) * QKV_O + HID + g * HD;
    const __half* vbase = kbase + KVH * HD;

    auto load_kv = [&](int buf, int j) {
        const __half* kp = kbase + (size_t)(j * 64) * QKV_O;
        const __half* vp = vbase + (size_t)(j * 64) * QKV_O;
        #pragma unroll
        for (int it = 0; it < 4; ++it) {
            int c = tid + it * 256;
            int row = c >> 4, col = (c & 15) * 8;
            CP_ASYNC16(ks[buf] + (row * KV_LD + col) * 2, kp + (size_t)row * QKV_O + col);
            CP_ASYNC16(vs[buf] + (row * KV_LD + col) * 2, vp + (size_t)row * QKV_O + col);
        }
    };

    const int jmax = 2 * qt + 1;
    load_kv(0, 0);
    CP_COMMIT();

    for (int j = 0; j <= jmax; ++j) {
        const int buf = j & 1;
        if (j < jmax) { load_kv(buf ^ 1, j + 1); CP_COMMIT(); CP_WAIT1(); }
        else          { CP_WAIT0(); }
        __syncthreads();

        if (j * 64 <= qt * 128 + wm * 16 + 15) {
            float s[8][4];
            #pragma unroll
            for (int nf = 0; nf < 8; ++nf)
                #pragma unroll
                for (int r = 0; r < 4; ++r) s[nf][r] = 0.f;

            #pragma unroll
            for (int kd = 0; kd < 8; ++kd) {
                uint32_t bf[4][4];
                #pragma unroll
                for (int q = 0; q < 4; ++q)
                    ldm_x4(bf[q][0], bf[q][1], bf[q][2], bf[q][3],
                           ks[buf] + ((q * 16 + lr + (lg >> 1) * 8) * KV_LD
                                      + kd * 16 + (lg & 1) * 8) * 2);
                #pragma unroll
                for (int nf = 0; nf < 8; ++nf)
                    mma16816(s[nf], qf[kd], bf[nf >> 1][(nf & 1) * 2],
                             bf[nf >> 1][(nf & 1) * 2 + 1]);
            }

            #pragma unroll
            for (int nf = 0; nf < 8; ++nf)
                #pragma unroll
                for (int r = 0; r < 4; ++r) s[nf][r] *= scale;

            if (j >= 2 * qt) {
                const int gr0 = qt * 128 + wm * 16 + r0;
                #pragma unroll
                for (int nf = 0; nf < 8; ++nf) {
                    int col = j * 64 + nf * 8 + c0;
                    if (col     > gr0)     s[nf][0] = -1e30f;
                    if (col + 1 > gr0)     s[nf][1] = -1e30f;
                    if (col     > gr0 + 8) s[nf][2] = -1e30f;
                    if (col + 1 > gr0 + 8) s[nf][3] = -1e30f;
                }
            }

            float t0m = -1e30f, t1m = -1e30f;
            #pragma unroll
            for (int nf = 0; nf < 8; ++nf) {
                t0m = fmaxf(t0m, fmaxf(s[nf][0], s[nf][1]));
                t1m = fmaxf(t1m, fmaxf(s[nf][2], s[nf][3]));
            }
            t0m = fmaxf(t0m, __shfl_xor_sync(0xffffffffu, t0m, 1));
            t0m = fmaxf(t0m, __shfl_xor_sync(0xffffffffu, t0m, 2));
            t1m = fmaxf(t1m, __shfl_xor_sync(0xffffffffu, t1m, 1));
            t1m = fmaxf(t1m, __shfl_xor_sync(0xffffffffu, t1m, 2));

            const float mn0 = fmaxf(m_i[0], t0m);
            const float mn1 = fmaxf(m_i[1], t1m);
            const float a0 = __expf(m_i[0] - mn0);
            const float a1 = __expf(m_i[1] - mn1);
            m_i[0] = mn0; m_i[1] = mn1;

            float rs0 = 0.f, rs1 = 0.f;
            #pragma unroll
            for (int nf = 0; nf < 8; ++nf) {
                s[nf][0] = __expf(s[nf][0] - mn0);
                s[nf][1] = __expf(s[nf][1] - mn0);
                s[nf][2] = __expf(s[nf][2] - mn1);
                s[nf][3] = __expf(s[nf][3] - mn1);
                rs0 += s[nf][0] + s[nf][1];
                rs1 += s[nf][2] + s[nf][3];
            }
            rs0 += __shfl_xor_sync(0xffffffffu, rs0, 1);
            rs0 += __shfl_xor_sync(0xffffffffu, rs0, 2);
            rs1 += __shfl_xor_sync(0xffffffffu, rs1, 1);
            rs1 += __shfl_xor_sync(0xffffffffu, rs1, 2);
            l_i[0] = l_i[0] * a0 + rs0;
            l_i[1] = l_i[1] * a1 + rs1;

            #pragma unroll
            for (int of = 0; of < 16; ++of) {
                o[of][0] *= a0; o[of][1] *= a0;
                o[of][2] *= a1; o[of][3] *= a1;
            }

            uint32_t pa[4][4];
            #pragma unroll
            for (int kc = 0; kc < 4; ++kc) {
                pa[kc][0] = f22h(s[2 * kc][0],     s[2 * kc][1]);
                pa[kc][1] = f22h(s[2 * kc][2],     s[2 * kc][3]);
                pa[kc][2] = f22h(s[2 * kc + 1][0], s[2 * kc + 1][1]);
                pa[kc][3] = f22h(s[2 * kc + 1][2], s[2 * kc + 1][3]);
            }

            #pragma unroll
            for (int kc = 0; kc < 4; ++kc) {
                #pragma unroll
                for (int dg = 0; dg < 8; ++dg) {
                    uint32_t vb[4];
                    ldm_x4_t(vb[0], vb[1], vb[2], vb[3],
                             vs[buf] + ((kc * 16 + lr + (lg & 1) * 8) * KV_LD
                                        + dg * 16 + (lg >> 1) * 8) * 2);
                    mma16816(o[dg * 2],     pa[kc], vb[0], vb[1]);
                    mma16816(o[dg * 2 + 1], pa[kc], vb[2], vb[3]);
                }
            }
        }
        __syncthreads();
    }

    const float inv0 = 1.f / l_i[0];
    const float inv1 = 1.f / l_i[1];
    __half* op = attnh + (size_t)(t0 + wm * 16) * HID + h * HD;
    #pragma unroll
    for (int of = 0; of < 16; ++of) {
        int col = of * 8 + c0;
        *(uint32_t*)(op + (size_t)r0 * HID + col)       = f22h(o[of][0] * inv0, o[of][1] * inv0);
        *(uint32_t*)(op + (size_t)(r0 + 8) * HID + col) = f22h(o[of][2] * inv1, o[of][3] * inv1);
    }
}

// ---------------------------------------------------------------------------
extern "C" void kernel_launch(void* const* d_in, const int* in_sizes, int n_in,
                              void* d_out, int out_size)
{
    const float* hs   = (const float*)d_in[0];
    const int*   pos  = (const int*)  d_in[1];
    const float* wqkv = (const float*)d_in[2];
    const float* wo   = (const float*)d_in[3];
    float* out = (float*)d_out;

    float* qkv;
    __half *qkv16, *hs16, *wqkv16, *wo16, *attn16;
    cudaGetSymbolAddress((void**)&qkv,    g_qkv);
    cudaGetSymbolAddress((void**)&qkv16,  g_qkv16);
    cudaGetSymbolAddress((void**)&hs16,   g_hs16);
    cudaGetSymbolAddress((void**)&wqkv16, g_wqkv16);
    cudaGetSymbolAddress((void**)&wo16,   g_wo16);
    cudaGetSymbolAddress((void**)&attn16, g_attn16);

    cudaFuncSetAttribute(hgemm_mma, cudaFuncAttributeMaxDynamicSharedMemorySize, GEMM_SMEM);
    cudaFuncSetAttribute(attn16_kernel, cudaFuncAttributeMaxDynamicSharedMemorySize, ATTN_SMEM);

    // 0) fp32 -> fp16 input conversions
    {
        int n;
        n = MROWS * HID;   cvt16<<<(n / 4 + 255) / 256, 256>>>(hs,   hs16,   n);
        n = QKV_O * HID;   cvt16<<<(n / 4 + 255) / 256, 256>>>(wqkv, wqkv16, n);
        n = HID * HID;     cvt16<<<(n / 4 + 255) / 256, 256>>>(wo,   wo16,   n);
    }

    // 1) QKV projection (fp16 tensor-core, fp32 out)
    hgemm_mma<<<dim3(QKV_O / 128, MROWS / 128), 256, GEMM_SMEM>>>(
        hs16, wqkv16, qkv, QKV_O, HID);

    // 2) fused RoPE + fp32->fp16
    {
        int total = MROWS * 3072;
        rope_cvt<<<(total + 255) / 256, 256>>>(qkv, qkv16, pos);
    }

    // 3) fp16 tensor-core flash attention -> fp16 out
    attn16_kernel<<<dim3(SQ / 128, NHEADS, BATCH), 256, ATTN_SMEM>>>(qkv16, attn16);

    // 4) O projection
    hgemm_mma<<<dim3(HID / 128, MROWS / 128), 256, GEMM_SMEM>>>(
        attn16, wo16, out, HID, HID);
}